// round 16
// baseline (speedup 1.0000x reference)
#include <cuda_runtime.h>
#include <cuda_bf16.h>
#include <math.h>
#include <float.h>

#define Bb 16
#define Ss 128
#define Tt 128
#define Hh 1024
#define Vv 32000
#define BOSTOK 1
#define GRIDB 128u

// ---------------- scratch (device globals; no allocs allowed) ----------------
__device__ float g_kproj[Bb * Ss * Hh];
__device__ float g_H[(Tt + 1) * Bb * Hh];
__device__ __nv_bfloat16 g_Hbf[Tt * Bb * Hh];
__device__ __nv_bfloat16 g_Woutbf[(size_t)Vv * Hh];
__device__ __nv_bfloat16 g_embbf[Tt * Bb * Hh];
__device__ __nv_bfloat16 g_Wihembbf[3 * Hh * Hh];
__device__ float g_gxemb[Tt * Bb * 3 * Hh];
__device__ __nv_bfloat16 g_Wcat_hi[4 * Hh * Hh];
__device__ __nv_bfloat16 g_Wcat_lo[4 * Hh * Hh];
__device__ __nv_bfloat16 g_enc_hi[Bb * Ss * Hh], g_enc_lo[Bb * Ss * Hh];
__device__ __nv_bfloat16 g_Wcp_hi[3 * Hh * Hh], g_Wcp_lo[3 * Hh * Hh];
__device__ __nv_bfloat16 g_Wk_hi[Hh * Hh], g_Wk_lo[Hh * Hh];
__device__ float g_encWc[(size_t)Bb * Ss * 3 * Hh];
__device__ float2 g_lsep[(size_t)Tt * Bb * (Vv / 64)];
__device__ __nv_bfloat16 g_hhi[Bb * Hh], g_hlo[Bb * Hh];
__device__ float g_q2[2][Bb * Hh];
__device__ float g_gh2[2][Bb * 3 * Hh];
__device__ float g_scores[Bb * Ss];
__device__ unsigned g_barcnt;
__device__ unsigned g_gbars[16 * 32];

// ---------------- math helpers ----------------
__device__ __forceinline__ float fast_tanh(float x) {
    float xc = fminf(fmaxf(x, -15.f), 15.f);
    float t = __expf(2.f * xc);
    return __fdividef(t - 1.f, t + 1.f);
}
__device__ __forceinline__ float fast_sigmoid(float x) {
    return __fdividef(1.f, 1.f + __expf(-x));
}
__device__ __forceinline__ float tanh_approx(float x) {
    float y;
    asm("tanh.approx.f32 %0, %1;" : "=f"(y) : "f"(x));
    return y;
}
__device__ __forceinline__ uint2 f4_to_bf8(float4 v) {
    __nv_bfloat162 lo = __floats2bfloat162_rn(v.x, v.y);
    __nv_bfloat162 hi = __floats2bfloat162_rn(v.z, v.w);
    uint2 o;
    o.x = *(const unsigned int*)&lo;
    o.y = *(const unsigned int*)&hi;
    return o;
}
__device__ __forceinline__ void split_f4(float4 v, uint2* hi, uint2* lo)
{
    __nv_bfloat16 hx = __float2bfloat16(v.x), hy = __float2bfloat16(v.y);
    __nv_bfloat16 hz = __float2bfloat16(v.z), hw = __float2bfloat16(v.w);
    float4 r = make_float4(v.x - __bfloat162float(hx), v.y - __bfloat162float(hy),
                           v.z - __bfloat162float(hz), v.w - __bfloat162float(hw));
    __nv_bfloat162 h01; h01.x = hx; h01.y = hy;
    __nv_bfloat162 h23; h23.x = hz; h23.y = hw;
    uint2 h; h.x = *(unsigned int*)&h01; h.y = *(unsigned int*)&h23;
    *hi = h;
    *lo = f4_to_bf8(r);
}

// ---------------- cp.async / ldmatrix helpers ----------------
__device__ __forceinline__ unsigned int smem_u32p(const void* p) {
    return (unsigned int)__cvta_generic_to_shared(p);
}
#define CPA16(dst_u32, src_ptr) \
    asm volatile("cp.async.ca.shared.global [%0], [%1], 16;" :: "r"(dst_u32), "l"(src_ptr))
#define CPA16CG(dst_u32, src_ptr) \
    asm volatile("cp.async.cg.shared.global [%0], [%1], 16;" :: "r"(dst_u32), "l"(src_ptr))
#define CPA_COMMIT() asm volatile("cp.async.commit_group;")
#define CPA_WAIT(n)  asm volatile("cp.async.wait_group %0;" :: "n"(n))

__device__ __forceinline__ void ldsm_x4(unsigned int* r, unsigned int addr) {
    asm volatile("ldmatrix.sync.aligned.m8n8.x4.shared.b16 {%0,%1,%2,%3}, [%4];"
        : "=r"(r[0]), "=r"(r[1]), "=r"(r[2]), "=r"(r[3]) : "r"(addr));
}
__device__ __forceinline__ void ldsm_x2(unsigned int* r, unsigned int addr) {
    asm volatile("ldmatrix.sync.aligned.m8n8.x2.shared.b16 {%0,%1}, [%2];"
        : "=r"(r[0]), "=r"(r[1]) : "r"(addr));
}

// ---------------- grid barriers (all GRIDB blocks resident) ------------------
__device__ __forceinline__ void bar_full(unsigned& bo) {
    bo += GRIDB;
    __syncthreads();
    if (threadIdx.x == 0) {
        __threadfence();
        atomicAdd(&g_barcnt, 1u);
        while (*((volatile unsigned*)&g_barcnt) < bo) { }
        __threadfence();
    }
    __syncthreads();
}
__device__ __forceinline__ void bar_group(unsigned ng) {
    __syncthreads();
    if (threadIdx.x == 0) {
        __threadfence();
        const unsigned idx = (blockIdx.x >> 3) << 5;
        atomicAdd(&g_gbars[idx], 1u);
        const unsigned tgt = ng << 3;
        while (*(volatile unsigned*)&g_gbars[idx] < tgt) { }
        __threadfence();
    }
    __syncthreads();
}

// ---------------- one-time conversions / gathers ----------------
__global__ __launch_bounds__(256) void conv_wout_kernel(const float* __restrict__ W)
{
    size_t n4 = (size_t)Vv * Hh / 4;
    uint2* dst = (uint2*)g_Woutbf;
    const float4* src = (const float4*)W;
    for (size_t i = blockIdx.x * 256 + threadIdx.x; i < n4; i += (size_t)gridDim.x * 256)
        dst[i] = f4_to_bf8(src[i]);
}

__global__ __launch_bounds__(256) void conv_wihemb_kernel(const float* __restrict__ Wih)
{
    int j = blockIdx.x;
    int c = threadIdx.x * 4;
    float4 v = *(const float4*)(Wih + (size_t)j * (2 * Hh) + c);
    *(uint2*)(g_Wihembbf + (size_t)j * Hh + c) = f4_to_bf8(v);
}

__global__ __launch_bounds__(256) void conv_wcat_kernel(
    const float* __restrict__ Wq, const float* __restrict__ Whh)
{
    int r = blockIdx.x;
    const float* src = (r < Hh) ? (Wq + (size_t)r * Hh) : (Whh + (size_t)(r - Hh) * Hh);
    int c = threadIdx.x * 4;
    float4 v = *(const float4*)(src + c);
    uint2 hi, lo;
    split_f4(v, &hi, &lo);
    *(uint2*)(g_Wcat_hi + (size_t)r * Hh + c) = hi;
    *(uint2*)(g_Wcat_lo + (size_t)r * Hh + c) = lo;
}

__global__ __launch_bounds__(256) void conv_split_kernel(
    const float* __restrict__ src, __nv_bfloat16* __restrict__ dhi,
    __nv_bfloat16* __restrict__ dlo)
{
    int r = blockIdx.x;
    int c = threadIdx.x * 4;
    float4 v = *(const float4*)(src + (size_t)r * Hh + c);
    uint2 hi, lo;
    split_f4(v, &hi, &lo);
    *(uint2*)(dhi + (size_t)r * Hh + c) = hi;
    *(uint2*)(dlo + (size_t)r * Hh + c) = lo;
}

__global__ __launch_bounds__(256) void conv_wcp_kernel(const float* __restrict__ Wih)
{
    int cidx = blockIdx.x;
    int J = cidx / 384;
    int r = cidx % 384;
    int g = r >> 7;
    int l = r & 127;
    int j = J * 128 + l;
    const float* src = Wih + (size_t)(g * Hh + j) * (2 * Hh) + Hh;
    int c = threadIdx.x * 4;
    float4 v = *(const float4*)(src + c);
    uint2 hi, lo;
    split_f4(v, &hi, &lo);
    *(uint2*)(g_Wcp_hi + (size_t)cidx * Hh + c) = hi;
    *(uint2*)(g_Wcp_lo + (size_t)cidx * Hh + c) = lo;
}

__global__ __launch_bounds__(256) void gather_emb_kernel(
    const float* __restrict__ emb, const int* __restrict__ tgt)
{
    int r = blockIdx.x;
    int t = r >> 4, b = r & 15;
    int tok = (t == 0) ? BOSTOK : tgt[b * Tt + (t - 1)];
    int c = threadIdx.x * 4;
    float4 v = *(const float4*)(emb + (size_t)tok * Hh + c);
    *(uint2*)(g_embbf + (size_t)r * Hh + c) = f4_to_bf8(v);
}

// ---------------- h0 init (also resets barriers) / hT copy ----------------
__global__ void init_h_kernel(const float* __restrict__ h0) {
    int i = blockIdx.x * 256 + threadIdx.x;
    if (i == 0) g_barcnt = 0;
    if (i < 16 * 32) g_gbars[i] = 0;
    if (i < Bb * Hh) {
        float v = h0[i];
        g_H[i] = v;
        __nv_bfloat16 hi = __float2bfloat16(v);
        g_hhi[i] = hi;
        g_hlo[i] = __float2bfloat16(v - __bfloat162float(hi));
    }
}
__global__ void copy_hT_kernel(float* __restrict__ dst) {
    int i = blockIdx.x * 256 + threadIdx.x;
    if (i < Bb * Hh) dst[i] = g_H[(size_t)Tt * Bb * Hh + i];
}

// ---------------- mma primitive ----------------
__device__ __forceinline__ void mma16816(float* c, unsigned int a0, unsigned int a1,
                                         unsigned int a2, unsigned int a3,
                                         unsigned int b0, unsigned int b1)
{
    asm volatile(
        "mma.sync.aligned.m16n8k16.row.col.f32.bf16.bf16.f32 "
        "{%0,%1,%2,%3}, {%4,%5,%6,%7}, {%8,%9}, {%0,%1,%2,%3};\n"
        : "+f"(c[0]), "+f"(c[1]), "+f"(c[2]), "+f"(c[3])
        : "r"(a0), "r"(a1), "r"(a2), "r"(a3), "r"(b0), "r"(b1));
}

// ---- big bf16 TC GEMM: ldmatrix fragments, 4-stage cp.async, 1 sync/iter ----
#define MMA_SMEM (4 * 128 * 40 * 2 + 4 * 64 * 40 * 2)
__global__ __launch_bounds__(256) void bf16_mma_kernel(
    const __nv_bfloat16* __restrict__ A, const __nv_bfloat16* __restrict__ Bm,
    const float* __restrict__ bias, float* __restrict__ out,
    float2* __restrict__ lsep, int N, int remap)
{
    extern __shared__ __align__(16) __nv_bfloat16 smem[];
    __nv_bfloat16 (*sA)[128][40] = (__nv_bfloat16(*)[128][40])smem;
    __nv_bfloat16 (*sB)[64][40]  = (__nv_bfloat16(*)[64][40])(smem + 4 * 128 * 40);

    const int tid = threadIdx.x;
    const int warp = tid >> 5;
    const int lane = tid & 31;
    const int wm = (warp & 3) * 32;
    const int wn = (warp >> 2) * 32;
    const int bm = blockIdx.y * 128;
    const int bn = blockIdx.x * 64;

    const int lr = tid >> 2;
    const int lc = (tid & 3) * 8;
    const int aRow = (lane & 7) + ((lane >> 3) & 1) * 8;
    const int aCol = ((lane >> 4) & 1) * 8;
    const int bRow = (lane & 7) + ((lane >> 4) & 1) * 8;
    const int bCol = ((lane >> 3) & 1) * 8;

    const __nv_bfloat16* Abase = A + (size_t)(bm + lr) * Hh + lc;
    const __nv_bfloat16* A2base = A + (size_t)(bm + lr + 64) * Hh + lc;
    const __nv_bfloat16* Bbase = Bm + (size_t)(bn + lr) * Hh + lc;

    float acc[2][4][4] = {};
    const int row = lane >> 2;
    const int kc = (lane & 3) * 2;

    auto issue = [&](int st, int k0) {
        CPA16(smem_u32p(&sA[st][lr][lc]), Abase + k0);
        CPA16(smem_u32p(&sA[st][lr + 64][lc]), A2base + k0);
        CPA16(smem_u32p(&sB[st][lr][lc]), Bbase + k0);
        CPA_COMMIT();
    };

    issue(0, 0);
    issue(1, 32);
    for (int k = 0; k < 32; k++) {
        const int st = k & 3;
        if (k + 2 < 32) { issue((k + 2) & 3, (k + 2) * 32); CPA_WAIT(2); }
        else if (k + 2 == 32) CPA_WAIT(1);
        else CPA_WAIT(0);
        __syncthreads();
#pragma unroll
        for (int kk = 0; kk < 32; kk += 16) {
            unsigned int a[2][4], b[4][2];
#pragma unroll
            for (int mf = 0; mf < 2; mf++)
                ldsm_x4(a[mf], smem_u32p(&sA[st][wm + mf * 16 + aRow][kk + aCol]));
#pragma unroll
            for (int nfp = 0; nfp < 2; nfp++) {
                unsigned int tmp[4];
                ldsm_x4(tmp, smem_u32p(&sB[st][wn + nfp * 16 + bRow][kk + bCol]));
                b[2 * nfp][0] = tmp[0]; b[2 * nfp][1] = tmp[1];
                b[2 * nfp + 1][0] = tmp[2]; b[2 * nfp + 1][1] = tmp[3];
            }
#pragma unroll
            for (int mf = 0; mf < 2; mf++)
#pragma unroll
                for (int nf = 0; nf < 4; nf++)
                    mma16816(acc[mf][nf], a[mf][0], a[mf][1], a[mf][2], a[mf][3],
                             b[nf][0], b[nf][1]);
        }
    }

    float mx[4] = {-FLT_MAX, -FLT_MAX, -FLT_MAX, -FLT_MAX};
    float se[4] = {0.f, 0.f, 0.f, 0.f};
#pragma unroll
    for (int mf = 0; mf < 2; mf++) {
#pragma unroll
        for (int nf = 0; nf < 4; nf++) {
            int gm = bm + wm + mf * 16 + row;
            int gn = bn + wn + nf * 8 + kc;
            float bi0 = bias[gn], bi1 = bias[gn + 1];
            float x0 = acc[mf][nf][0] + bi0, x1 = acc[mf][nf][1] + bi1;
            float x2 = acc[mf][nf][2] + bi0, x3 = acc[mf][nf][3] + bi1;
            int o0 = remap ? ((gm & 15) * Tt + (gm >> 4)) : gm;
            int gm2 = gm + 8;
            int o1 = remap ? ((gm2 & 15) * Tt + (gm2 >> 4)) : gm2;
            *(float2*)(out + (size_t)o0 * N + gn) = make_float2(x0, x1);
            *(float2*)(out + (size_t)o1 * N + gn) = make_float2(x2, x3);
            if (lsep) {
                int r0i = mf * 2, r1i = mf * 2 + 1;
                float nm0 = fmaxf(mx[r0i], fmaxf(x0, x1));
                se[r0i] = se[r0i] * __expf(mx[r0i] - nm0) + __expf(x0 - nm0) + __expf(x1 - nm0);
                mx[r0i] = nm0;
                float nm1 = fmaxf(mx[r1i], fmaxf(x2, x3));
                se[r1i] = se[r1i] * __expf(mx[r1i] - nm1) + __expf(x2 - nm1) + __expf(x3 - nm1);
                mx[r1i] = nm1;
            }
        }
    }

    if (lsep) {
#pragma unroll
        for (int rr = 0; rr < 4; rr++) {
#pragma unroll
            for (int o = 1; o <= 2; o <<= 1) {
                float m2 = __shfl_xor_sync(~0u, mx[rr], o);
                float s2 = __shfl_xor_sync(~0u, se[rr], o);
                float nm = fmaxf(mx[rr], m2);
                se[rr] = se[rr] * __expf(mx[rr] - nm) + s2 * __expf(m2 - nm);
                mx[rr] = nm;
            }
        }
        __syncthreads();
        float2 (*sLse)[128] = (float2(*)[128])smem;
        if ((lane & 3) == 0) {
#pragma unroll
            for (int rr = 0; rr < 4; rr++) {
                int mrow = wm + (rr >> 1) * 16 + row + (rr & 1) * 8;
                sLse[warp >> 2][mrow] = make_float2(mx[rr], se[rr]);
            }
        }
        __syncthreads();
        if (tid < 128) {
            float2 p0 = sLse[0][tid], p1 = sLse[1][tid];
            float nm = fmaxf(p0.x, p1.x);
            float s = p0.y * __expf(p0.x - nm) + p1.y * __expf(p1.x - nm);
            int gm = bm + tid;
            int o = remap ? ((gm & 15) * Tt + (gm >> 4)) : gm;
            lsep[(size_t)o * gridDim.x + blockIdx.x] = make_float2(nm, s);
        }
    }
}

// ---- split GEMM (generic): out(fp32) = Ah@Bh^T + Ah@Bl^T + Al@Bh^T ----------
#define SPLIT_SMEM 61440
__global__ __launch_bounds__(256) void split_mma_kernel(
    const __nv_bfloat16* __restrict__ Ahp, const __nv_bfloat16* __restrict__ Alp,
    const __nv_bfloat16* __restrict__ Bhp, const __nv_bfloat16* __restrict__ Blp,
    float* __restrict__ out, int N)
{
    extern __shared__ __align__(16) __nv_bfloat16 sm[];
    __nv_bfloat16 (*sAh)[128][40] = (__nv_bfloat16(*)[128][40])sm;
    __nv_bfloat16 (*sAl)[128][40] = (__nv_bfloat16(*)[128][40])(sm + 2 * 128 * 40);
    __nv_bfloat16 (*sBh)[64][40]  = (__nv_bfloat16(*)[64][40]) (sm + 4 * 128 * 40);
    __nv_bfloat16 (*sBl)[64][40]  = (__nv_bfloat16(*)[64][40]) (sm + 4 * 128 * 40 + 2 * 64 * 40);

    const int tid = threadIdx.x;
    const int warp = tid >> 5;
    const int lane = tid & 31;
    const int wm = (warp & 3) * 32;
    const int wn = (warp >> 2) * 32;
    const int bm = blockIdx.y * 128;
    const int bn = blockIdx.x * 64;
    const int lr = tid >> 2;
    const int lc = (tid & 3) * 8;
    const int row = lane >> 2;
    const int kc = (lane & 3) * 2;
    const int aRow = (lane & 7) + ((lane >> 3) & 1) * 8;
    const int aCol = ((lane >> 4) & 1) * 8;
    const int bRow = (lane & 7) + ((lane >> 4) & 1) * 8;
    const int bCol = ((lane >> 3) & 1) * 8;

    const __nv_bfloat16* Ah1 = Ahp + (size_t)(bm + lr) * Hh + lc;
    const __nv_bfloat16* Ah2 = Ahp + (size_t)(bm + lr + 64) * Hh + lc;
    const __nv_bfloat16* Al1 = Alp + (size_t)(bm + lr) * Hh + lc;
    const __nv_bfloat16* Al2 = Alp + (size_t)(bm + lr + 64) * Hh + lc;
    const __nv_bfloat16* Bh1 = Bhp + (size_t)(bn + lr) * Hh + lc;
    const __nv_bfloat16* Bl1 = Blp + (size_t)(bn + lr) * Hh + lc;

    float acc[2][4][4] = {};

    auto issue = [&](int st, int k0) {
        CPA16(smem_u32p(&sAh[st][lr][lc]),      Ah1 + k0);
        CPA16(smem_u32p(&sAh[st][lr + 64][lc]), Ah2 + k0);
        CPA16(smem_u32p(&sAl[st][lr][lc]),      Al1 + k0);
        CPA16(smem_u32p(&sAl[st][lr + 64][lc]), Al2 + k0);
        CPA16(smem_u32p(&sBh[st][lr][lc]),      Bh1 + k0);
        CPA16(smem_u32p(&sBl[st][lr][lc]),      Bl1 + k0);
        CPA_COMMIT();
    };

    issue(0, 0);
    for (int k = 0; k < 32; k++) {
        const int st = k & 1;
        if (k + 1 < 32) { issue(st ^ 1, (k + 1) * 32); CPA_WAIT(1); }
        else            { CPA_WAIT(0); }
        __syncthreads();
#pragma unroll
        for (int kk = 0; kk < 32; kk += 16) {
            unsigned int ah[2][4], al[2][4], bh[4][2], bl[4][2];
#pragma unroll
            for (int mf = 0; mf < 2; mf++) {
                ldsm_x4(ah[mf], smem_u32p(&sAh[st][wm + mf * 16 + aRow][kk + aCol]));
                ldsm_x4(al[mf], smem_u32p(&sAl[st][wm + mf * 16 + aRow][kk + aCol]));
            }
#pragma unroll
            for (int nfp = 0; nfp < 2; nfp++) {
                unsigned int th[4], tl[4];
                ldsm_x4(th, smem_u32p(&sBh[st][wn + nfp * 16 + bRow][kk + bCol]));
                ldsm_x4(tl, smem_u32p(&sBl[st][wn + nfp * 16 + bRow][kk + bCol]));
                bh[2 * nfp][0] = th[0]; bh[2 * nfp][1] = th[1];
                bh[2 * nfp + 1][0] = th[2]; bh[2 * nfp + 1][1] = th[3];
                bl[2 * nfp][0] = tl[0]; bl[2 * nfp][1] = tl[1];
                bl[2 * nfp + 1][0] = tl[2]; bl[2 * nfp + 1][1] = tl[3];
            }
#pragma unroll
            for (int mf = 0; mf < 2; mf++)
#pragma unroll
                for (int nf = 0; nf < 4; nf++) {
                    mma16816(acc[mf][nf], ah[mf][0], ah[mf][1], ah[mf][2], ah[mf][3],
                             bh[nf][0], bh[nf][1]);
                    mma16816(acc[mf][nf], ah[mf][0], ah[mf][1], ah[mf][2], ah[mf][3],
                             bl[nf][0], bl[nf][1]);
                    mma16816(acc[mf][nf], al[mf][0], al[mf][1], al[mf][2], al[mf][3],
                             bh[nf][0], bh[nf][1]);
                }
        }
        __syncthreads();
    }

#pragma unroll
    for (int mf = 0; mf < 2; mf++) {
#pragma unroll
        for (int nf = 0; nf < 4; nf++) {
            int gm = bm + wm + mf * 16 + row;
            int gn = bn + wn + nf * 8 + kc;
            *(float2*)(out + (size_t)gm * N + gn) =
                make_float2(acc[mf][nf][0], acc[mf][nf][1]);
            *(float2*)(out + (size_t)(gm + 8) * N + gn) =
                make_float2(acc[mf][nf][2], acc[mf][nf][3]);
        }
    }
}

// ---------------- persistent decode loop: 128 blocks x 256 threads -----------
struct SmemA { __nv_bfloat16 Ah[4][16][72], Al[4][16][72], Bh[4][64][72], Bl[4][64][72]; };
struct SmemB { float q[Hh]; float v[Hh]; };
struct SmemC { float w[Ss]; float part[3][128]; float sred[4]; float sred2[4]; };
#define LOOP_SMEM 92160

__global__ __launch_bounds__(256) void loop_kernel(
    const float* __restrict__ vat, const float* __restrict__ bhh,
    float* __restrict__ attw)
{
    extern __shared__ __align__(16) unsigned char sraw[];

    const int g = blockIdx.x;
    const int tid = threadIdx.x;
    const int warp = tid >> 5;
    const int lane = tid & 31;
    const int row = lane >> 2;
    const int kc = (lane & 3) * 2;
    const int lrB = tid >> 2;
    const int lcB = (tid & 3) * 16;
    const int rA = (tid & 63) >> 2;
    const int cA = (tid & 3) * 16;
    const int wn = warp * 8;
    const int aRow = (lane & 7) + ((lane >> 3) & 1) * 8;
    const int aCol = ((lane >> 4) & 1) * 8;
    const int bRow2 = (lane & 7);
    const int bCol2 = ((lane >> 3) & 1) * 8;
    unsigned nfull = 0, ngrp = 0;

    const int ntA = g & 63, ksA = g >> 6;
    const int bnA = ntA * 64, kbA = ksA * 512;
    const __nv_bfloat16* gBhA = g_Wcat_hi + (size_t)(bnA + lrB) * Hh + kbA + lcB;
    const __nv_bfloat16* gBlA = g_Wcat_lo + (size_t)(bnA + lrB) * Hh + kbA + lcB;
    const __nv_bfloat16* gAhA = g_hhi + (size_t)rA * Hh + kbA + cA;
    const __nv_bfloat16* gAlA = g_hlo + (size_t)rA * Hh + kbA + cA;

    const int bB = g >> 3, sbB = (g & 7) * 16;
    const int bC = g >> 3, hcC = g & 7;

    for (int t = 0; t < Tt; t++) {
        // ================= stage A: [q | gh] partials (K-split 2) =============
        {
            SmemA& sa = *reinterpret_cast<SmemA*>(sraw);
            float c0[4] = {}, c1[4] = {}, c2[4] = {};

            auto issueA = [&](int st, int k0) {
                if (tid < 64) {
                    CPA16CG(smem_u32p(&sa.Ah[st][rA][cA]),     gAhA + k0);
                    CPA16CG(smem_u32p(&sa.Ah[st][rA][cA + 8]), gAhA + k0 + 8);
                } else if (tid < 128) {
                    CPA16CG(smem_u32p(&sa.Al[st][rA][cA]),     gAlA + k0);
                    CPA16CG(smem_u32p(&sa.Al[st][rA][cA + 8]), gAlA + k0 + 8);
                }
                CPA16(smem_u32p(&sa.Bh[st][lrB][lcB]),     gBhA + k0);
                CPA16(smem_u32p(&sa.Bh[st][lrB][lcB + 8]), gBhA + k0 + 8);
                CPA16(smem_u32p(&sa.Bl[st][lrB][lcB]),     gBlA + k0);
                CPA16(smem_u32p(&sa.Bl[st][lrB][lcB + 8]), gBlA + k0 + 8);
                CPA_COMMIT();
            };

            issueA(0, 0);
            issueA(1, 64);
            for (int k = 0; k < 8; k++) {
                const int st = k & 3;
                if (k + 2 < 8) { issueA((k + 2) & 3, (k + 2) * 64); CPA_WAIT(2); }
                else if (k + 2 == 8) CPA_WAIT(1);
                else CPA_WAIT(0);
                __syncthreads();
#pragma unroll
                for (int kk = 0; kk < 64; kk += 16) {
                    unsigned int ah[4], al[4], bh[2], bl[2];
                    ldsm_x4(ah, smem_u32p(&sa.Ah[st][aRow][kk + aCol]));
                    ldsm_x4(al, smem_u32p(&sa.Al[st][aRow][kk + aCol]));
                    ldsm_x2(bh, smem_u32p(&sa.Bh[st][wn + bRow2][kk + bCol2]));
                    ldsm_x2(bl, smem_u32p(&sa.Bl[st][wn + bRow2][kk + bCol2]));
                    mma16816(c0, ah[0], ah[1], ah[2], ah[3], bh[0], bh[1]);
                    mma16816(c1, ah[0], ah[1], ah[2], ah[3], bl[0], bl[1]);
                    mma16816(c2, al[0], al[1], al[2], al[3], bh[0], bh[1]);
                }
            }
            float v0 = c0[0] + c1[0] + c2[0];
            float v1 = c0[1] + c1[1] + c2[1];
            float v2 = c0[2] + c1[2] + c2[2];
            float v3 = c0[3] + c1[3] + c2[3];
            int gn = bnA + wn + kc;
            if (gn < Hh) {
                float* qd = g_q2[ksA];
                *(float2*)(qd + (size_t)row * Hh + gn)       = make_float2(v0, v1);
                *(float2*)(qd + (size_t)(row + 8) * Hh + gn) = make_float2(v2, v3);
            } else {
                int n = gn - Hh;
                float* gd = g_gh2[ksA];
                *(float2*)(gd + (size_t)row * 3 * Hh + n)       = make_float2(v0, v1);
                *(float2*)(gd + (size_t)(row + 8) * 3 * Hh + n) = make_float2(v2, v3);
            }
        }
        bar_full(nfull);

        // ================= stage B: scores (2 per warp, interleaved) ==========
        {
            SmemB& sb = *reinterpret_cast<SmemB*>(sraw);
            float4 q0 = __ldcg((const float4*)g_q2[0] + bB * 256 + tid);
            float4 q1 = __ldcg((const float4*)g_q2[1] + bB * 256 + tid);
            ((float4*)sb.q)[tid] = make_float4(q0.x + q1.x, q0.y + q1.y,
                                               q0.z + q1.z, q0.w + q1.w);
            ((float4*)sb.v)[tid] = __ldg((const float4*)vat + tid);
            __syncthreads();
            int s0 = sbB + warp * 2;
            const float4* kp0 = (const float4*)(g_kproj + (size_t)(bB * Ss + s0) * Hh);
            const float4* kp1 = kp0 + 256;
            float a0 = 0.f, a1 = 0.f;
#pragma unroll
            for (int i = 0; i < 8; i++) {
                int idx = i * 32 + lane;
                float4 ka = __ldg(kp0 + idx);
                float4 kb = __ldg(kp1 + idx);
                float4 q4 = ((const float4*)sb.q)[idx];
                float4 v4 = ((const float4*)sb.v)[idx];
                a0 = fmaf(v4.x, tanh_approx(q4.x + ka.x), a0);
                a1 = fmaf(v4.x, tanh_approx(q4.x + kb.x), a1);
                a0 = fmaf(v4.y, tanh_approx(q4.y + ka.y), a0);
                a1 = fmaf(v4.y, tanh_approx(q4.y + kb.y), a1);
                a0 = fmaf(v4.z, tanh_approx(q4.z + ka.z), a0);
                a1 = fmaf(v4.z, tanh_approx(q4.z + kb.z), a1);
                a0 = fmaf(v4.w, tanh_approx(q4.w + ka.w), a0);
                a1 = fmaf(v4.w, tanh_approx(q4.w + kb.w), a1);
            }
#pragma unroll
            for (int o = 16; o; o >>= 1) {
                a0 += __shfl_xor_sync(~0u, a0, o);
                a1 += __shfl_xor_sync(~0u, a1, o);
            }
            if (lane == 0) {
                g_scores[bB * Ss + s0] = a0;
                g_scores[bB * Ss + s0 + 1] = a1;
            }
        }
        bar_group(++ngrp);

        // ====== stage C': softmax + gx_ctx reduction + fused GRU + h write =====
        {
            SmemC& sc = *reinterpret_cast<SmemC*>(sraw);
            const int l = tid & 127;
            const int j = hcC * 128 + l;
            const int r = t * Bb + bC;

            // prefetch gate-tail operands (safe: gh2 ordered by post-A full bar)
            float gxe_r = 0.f, gxe_z = 0.f, gxe_n = 0.f;
            float gh_r = 0.f, gh_z = 0.f, gh_n = 0.f, hp = 0.f;
            if (tid < 128) {
                const float* gxe = g_gxemb + (size_t)r * 3 * Hh;
                const float* g0 = g_gh2[0] + (size_t)bC * 3 * Hh;
                const float* g1 = g_gh2[1] + (size_t)bC * 3 * Hh;
                gxe_r = gxe[j];
                gxe_z = gxe[Hh + j];
                gxe_n = gxe[2 * Hh + j];
                gh_r = __ldcg(g0 + j)          + __ldcg(g1 + j)          + bhh[j];
                gh_z = __ldcg(g0 + Hh + j)     + __ldcg(g1 + Hh + j)     + bhh[Hh + j];
                gh_n = __ldcg(g0 + 2 * Hh + j) + __ldcg(g1 + 2 * Hh + j) + bhh[2 * Hh + j];
                hp = g_H[(size_t)t * Bb * Hh + bC * Hh + j];
            }

            float sval = 0.f;
            if (tid < 128) {
                sval = __ldcg(g_scores + bC * Ss + tid);
                float mx = sval;
#pragma unroll
                for (int o = 16; o; o >>= 1) mx = fmaxf(mx, __shfl_xor_sync(~0u, mx, o));
                if ((tid & 31) == 0) sc.sred[tid >> 5] = mx;
            }
            __syncthreads();
            float mxx = fmaxf(fmaxf(sc.sred[0], sc.sred[1]), fmaxf(sc.sred[2], sc.sred[3]));
            float e = 0.f;
            if (tid < 128) {
                e = __expf(sval - mxx);
                float sm = e;
#pragma unroll
                for (int o = 16; o; o >>= 1) sm += __shfl_xor_sync(~0u, sm, o);
                if ((tid & 31) == 0) sc.sred2[tid >> 5] = sm;
            }
            __syncthreads();
            float tot = sc.sred2[0] + sc.sred2[1] + sc.sred2[2] + sc.sred2[3];
            if (tid < 128) {
                float wv = __fdividef(e, tot);
                sc.w[tid] = wv;
                if (hcC == 0) attw[((size_t)bC * Tt + t) * Ss + tid] = wv;
            }
            __syncthreads();

            const int sh = (tid >> 7) * 64;
            const float* ew = g_encWc + ((size_t)(bC * Ss + sh)) * (3 * Hh) + hcC * 384;
            const float* wp = sc.w + sh;
            float ar = 0.f, az = 0.f, an = 0.f;
#pragma unroll 8
            for (int s = 0; s < 64; s++) {
                float ws = wp[s];
                const float* rp = ew + (size_t)s * (3 * Hh);
                ar = fmaf(ws, __ldg(rp + l), ar);
                az = fmaf(ws, __ldg(rp + 128 + l), az);
                an = fmaf(ws, __ldg(rp + 256 + l), an);
            }
            if (tid >= 128) {
                sc.part[0][l] = ar; sc.part[1][l] = az; sc.part[2][l] = an;
            }
            __syncthreads();
            if (tid < 128) {
                ar += sc.part[0][l];
                az += sc.part[1][l];
                an += sc.part[2][l];
                float gx_r = ar + gxe_r;
                float gx_z = az + gxe_z;
                float gx_n = an + gxe_n;
                float rg = fast_sigmoid(gx_r + gh_r);
                float z  = fast_sigmoid(gx_z + gh_z);
                float nn = fast_tanh(gx_n + rg * gh_n);
                float hv = (1.f - z) * nn + z * hp;
                g_H[(size_t)(t + 1) * Bb * Hh + bC * Hh + j] = hv;
                g_Hbf[(size_t)r * Hh + j] = __float2bfloat16(hv);
                __nv_bfloat16 hi = __float2bfloat16(hv);
                g_hhi[bC * Hh + j] = hi;
                g_hlo[bC * Hh + j] = __float2bfloat16(hv - __bfloat162float(hi));
            }
        }
        bar_full(nfull);
    }
}

// -------- final: log_softmax using fused lse partials -------------------------
__global__ __launch_bounds__(256) void logsoftmax_kernel(
    float* __restrict__ out, const float2* __restrict__ lsep, int ntile)
{
    const int o = blockIdx.x;
    float* row = out + (size_t)o * Vv;
    int tid = threadIdx.x;
    __shared__ float smax[8], ssum[8];

    float m = -FLT_MAX, s = 0.f;
    for (int i = tid; i < ntile; i += 256) {
        float2 p = lsep[(size_t)o * ntile + i];
        float nm = fmaxf(m, p.x);
        s = s * __expf(m - nm) + p.y * __expf(p.x - nm);
        m = nm;
    }
#pragma unroll
    for (int off = 16; off; off >>= 1) {
        float m2 = __shfl_xor_sync(~0u, m, off);
        float s2 = __shfl_xor_sync(~0u, s, off);
        float nm = fmaxf(m, m2);
        s = s * __expf(m - nm) + s2 * __expf(m2 - nm);
        m = nm;
    }
    if ((tid & 31) == 0) { smax[tid >> 5] = m; ssum[tid >> 5] = s; }
    __syncthreads();
    float M = smax[0];
#pragma unroll
    for (int i = 1; i < 8; i++) M = fmaxf(M, smax[i]);
    float S = 0.f;
#pragma unroll
    for (int i = 0; i < 8; i++) S += ssum[i] * __expf(smax[i] - M);

    float lse = M + logf(S);
    for (int v = tid; v < Vv; v += 256) row[v] -= lse;
}

// ---------------- orchestration ----------------
extern "C" void kernel_launch(void* const* d_in, const int* in_sizes, int n_in,
                              void* d_out, int out_size)
{
    const float* enc  = (const float*)d_in[0];
    const float* h0   = (const float*)d_in[1];
    const int*   tgt  = (const int*)  d_in[2];
    const float* emb  = (const float*)d_in[3];
    const float* Wq   = (const float*)d_in[4];
    const float* Wk   = (const float*)d_in[5];
    const float* vat  = (const float*)d_in[6];
    const float* Wih  = (const float*)d_in[7];
    const float* Whh  = (const float*)d_in[8];
    const float* bih  = (const float*)d_in[9];
    const float* bhh  = (const float*)d_in[10];
    const float* Wout = (const float*)d_in[11];
    const float* bout = (const float*)d_in[12];

    float* out       = (float*)d_out;
    float* out_hT    = out + (size_t)Bb * Tt * Vv;
    float* out_attw  = out_hT + (size_t)Bb * Hh;

    (void)in_sizes; (void)n_in; (void)out_size;

    cudaFuncSetAttribute(loop_kernel, cudaFuncAttributeMaxDynamicSharedMemorySize, LOOP_SMEM);
    cudaFuncSetAttribute(split_mma_kernel, cudaFuncAttributeMaxDynamicSharedMemorySize, SPLIT_SMEM);
    cudaFuncSetAttribute(bf16_mma_kernel, cudaFuncAttributeMaxDynamicSharedMemorySize, MMA_SMEM);

    // Phase 0: one-time conversions / precomputes
    conv_wout_kernel<<<4096, 256>>>(Wout);
    conv_wihemb_kernel<<<3 * Hh, 256>>>(Wih);
    conv_wcat_kernel<<<4 * Hh, 256>>>(Wq, Whh);
    conv_wcp_kernel<<<3 * Hh, 256>>>(Wih);
    gather_emb_kernel<<<Tt * Bb, 256>>>(emb, tgt);
    {
        __nv_bfloat16 *embbf, *wihembbf, *enc_hi, *enc_lo, *wcp_hi, *wcp_lo, *wk_hi, *wk_lo;
        float *gxemb_ptr, *encWc, *kproj;
        cudaGetSymbolAddress((void**)&embbf, g_embbf);
        cudaGetSymbolAddress((void**)&wihembbf, g_Wihembbf);
        cudaGetSymbolAddress((void**)&gxemb_ptr, g_gxemb);
        cudaGetSymbolAddress((void**)&enc_hi, g_enc_hi);
        cudaGetSymbolAddress((void**)&enc_lo, g_enc_lo);
        cudaGetSymbolAddress((void**)&wcp_hi, g_Wcp_hi);
        cudaGetSymbolAddress((void**)&wcp_lo, g_Wcp_lo);
        cudaGetSymbolAddress((void**)&wk_hi, g_Wk_hi);
        cudaGetSymbolAddress((void**)&wk_lo, g_Wk_lo);
        cudaGetSymbolAddress((void**)&encWc, g_encWc);
        cudaGetSymbolAddress((void**)&kproj, g_kproj);

        conv_split_kernel<<<Bb * Ss, 256>>>(enc, enc_hi, enc_lo);
        conv_split_kernel<<<Hh, 256>>>(Wk, wk_hi, wk_lo);

        bf16_mma_kernel<<<dim3(3 * Hh / 64, (Tt * Bb) / 128), 256, MMA_SMEM>>>(
            embbf, wihembbf, bih, gxemb_ptr, nullptr, 3 * Hh, 0);
        split_mma_kernel<<<dim3(3 * Hh / 64, (Bb * Ss) / 128), 256, SPLIT_SMEM>>>(
            enc_hi, enc_lo, wcp_hi, wcp_lo, encWc, 3 * Hh);
        split_mma_kernel<<<dim3(Hh / 64, (Bb * Ss) / 128), 256, SPLIT_SMEM>>>(
            enc_hi, enc_lo, wk_hi, wk_lo, kproj, Hh);
    }
    init_h_kernel<<<(Bb * Hh + 255) / 256, 256>>>(h0);

    // Phase 2: entire sequential decode in ONE persistent kernel (3 syncs/step)
    loop_kernel<<<GRIDB, 256, LOOP_SMEM>>>(vat, bhh, out_attw);

    copy_hT_kernel<<<(Bb * Hh + 255) / 256, 256>>>(out_hT);

    // Phase 3: logits (ldmatrix + 4-stage + fused lse partials) + log_softmax
    {
        __nv_bfloat16 *Abf, *Bbf;
        float2* lsep;
        cudaGetSymbolAddress((void**)&Abf, g_Hbf);
        cudaGetSymbolAddress((void**)&Bbf, g_Woutbf);
        cudaGetSymbolAddress((void**)&lsep, g_lsep);
        bf16_mma_kernel<<<dim3(Vv / 64, (Tt * Bb) / 128), 256, MMA_SMEM>>>(
            Abf, Bbf, bout, out, lsep, Vv, 1);
        logsoftmax_kernel<<<Bb * Tt, 256>>>(out, lsep, Vv / 64);
    }
}

// round 17
// speedup vs baseline: 1.0866x; 1.0866x over previous
#include <cuda_runtime.h>
#include <cuda_bf16.h>
#include <math.h>
#include <float.h>

#define Bb 16
#define Ss 128
#define Tt 128
#define Hh 1024
#define Vv 32000
#define BOSTOK 1
#define GRIDB 128u

// ---------------- scratch (device globals; no allocs allowed) ----------------
__device__ float g_kproj[Bb * Ss * Hh];
__device__ float g_H[(Tt + 1) * Bb * Hh];
__device__ __nv_bfloat16 g_Hbf[Tt * Bb * Hh];
__device__ __nv_bfloat16 g_Woutbf[(size_t)Vv * Hh];
__device__ __nv_bfloat16 g_embbf[Tt * Bb * Hh];
__device__ __nv_bfloat16 g_Wihembbf[3 * Hh * Hh];
__device__ float g_gxemb[Tt * Bb * 3 * Hh];
__device__ __nv_bfloat16 g_Wcat_hi[4 * Hh * Hh];
__device__ __nv_bfloat16 g_Wcat_lo[4 * Hh * Hh];
__device__ __nv_bfloat16 g_enc_hi[Bb * Ss * Hh], g_enc_lo[Bb * Ss * Hh];
__device__ __nv_bfloat16 g_Wcp_hi[3 * Hh * Hh], g_Wcp_lo[3 * Hh * Hh];
__device__ __nv_bfloat16 g_Wk_hi[Hh * Hh], g_Wk_lo[Hh * Hh];
__device__ float g_encWc[(size_t)Bb * Ss * 3 * Hh];
__device__ float2 g_lsep[(size_t)Tt * Bb * (Vv / 64)];
__device__ __nv_bfloat16 g_hhi[Bb * Hh], g_hlo[Bb * Hh];
__device__ float g_q2[2][Bb * Hh];
__device__ float g_gh2[2][Bb * 3 * Hh];
__device__ float g_scores[Bb * Ss];
__device__ unsigned g_barcnt;
__device__ unsigned g_gbars[16 * 32];

// ---------------- math helpers ----------------
__device__ __forceinline__ float fast_tanh(float x) {
    float xc = fminf(fmaxf(x, -15.f), 15.f);
    float t = __expf(2.f * xc);
    return __fdividef(t - 1.f, t + 1.f);
}
__device__ __forceinline__ float fast_sigmoid(float x) {
    return __fdividef(1.f, 1.f + __expf(-x));
}
__device__ __forceinline__ float tanh_approx(float x) {
    float y;
    asm("tanh.approx.f32 %0, %1;" : "=f"(y) : "f"(x));
    return y;
}
__device__ __forceinline__ uint2 f4_to_bf8(float4 v) {
    __nv_bfloat162 lo = __floats2bfloat162_rn(v.x, v.y);
    __nv_bfloat162 hi = __floats2bfloat162_rn(v.z, v.w);
    uint2 o;
    o.x = *(const unsigned int*)&lo;
    o.y = *(const unsigned int*)&hi;
    return o;
}
__device__ __forceinline__ void split_f4(float4 v, uint2* hi, uint2* lo)
{
    __nv_bfloat16 hx = __float2bfloat16(v.x), hy = __float2bfloat16(v.y);
    __nv_bfloat16 hz = __float2bfloat16(v.z), hw = __float2bfloat16(v.w);
    float4 r = make_float4(v.x - __bfloat162float(hx), v.y - __bfloat162float(hy),
                           v.z - __bfloat162float(hz), v.w - __bfloat162float(hw));
    __nv_bfloat162 h01; h01.x = hx; h01.y = hy;
    __nv_bfloat162 h23; h23.x = hz; h23.y = hw;
    uint2 h; h.x = *(unsigned int*)&h01; h.y = *(unsigned int*)&h23;
    *hi = h;
    *lo = f4_to_bf8(r);
}

// ---------------- cp.async / ldmatrix helpers ----------------
__device__ __forceinline__ unsigned int smem_u32p(const void* p) {
    return (unsigned int)__cvta_generic_to_shared(p);
}
#define CPA16(dst_u32, src_ptr) \
    asm volatile("cp.async.ca.shared.global [%0], [%1], 16;" :: "r"(dst_u32), "l"(src_ptr))
#define CPA16CG(dst_u32, src_ptr) \
    asm volatile("cp.async.cg.shared.global [%0], [%1], 16;" :: "r"(dst_u32), "l"(src_ptr))
#define CPA_COMMIT() asm volatile("cp.async.commit_group;")
#define CPA_WAIT(n)  asm volatile("cp.async.wait_group %0;" :: "n"(n))

__device__ __forceinline__ void ldsm_x4(unsigned int* r, unsigned int addr) {
    asm volatile("ldmatrix.sync.aligned.m8n8.x4.shared.b16 {%0,%1,%2,%3}, [%4];"
        : "=r"(r[0]), "=r"(r[1]), "=r"(r[2]), "=r"(r[3]) : "r"(addr));
}
__device__ __forceinline__ void ldsm_x2(unsigned int* r, unsigned int addr) {
    asm volatile("ldmatrix.sync.aligned.m8n8.x2.shared.b16 {%0,%1}, [%2];"
        : "=r"(r[0]), "=r"(r[1]) : "r"(addr));
}

// ---------------- grid barriers (all GRIDB blocks resident) ------------------
__device__ __forceinline__ void bar_full(unsigned& bo) {
    bo += GRIDB;
    __syncthreads();
    if (threadIdx.x == 0) {
        __threadfence();
        atomicAdd(&g_barcnt, 1u);
        while (*((volatile unsigned*)&g_barcnt) < bo) { }
        __threadfence();
    }
    __syncthreads();
}
__device__ __forceinline__ void bar_group(unsigned ng) {
    __syncthreads();
    if (threadIdx.x == 0) {
        __threadfence();
        const unsigned idx = (blockIdx.x >> 3) << 5;
        atomicAdd(&g_gbars[idx], 1u);
        const unsigned tgt = ng << 3;
        while (*(volatile unsigned*)&g_gbars[idx] < tgt) { }
        __threadfence();
    }
    __syncthreads();
}

// ---------------- one-time conversions / gathers ----------------
__global__ __launch_bounds__(256) void conv_wout_kernel(const float* __restrict__ W)
{
    size_t n4 = (size_t)Vv * Hh / 4;
    uint2* dst = (uint2*)g_Woutbf;
    const float4* src = (const float4*)W;
    for (size_t i = blockIdx.x * 256 + threadIdx.x; i < n4; i += (size_t)gridDim.x * 256)
        dst[i] = f4_to_bf8(src[i]);
}

__global__ __launch_bounds__(256) void conv_wihemb_kernel(const float* __restrict__ Wih)
{
    int j = blockIdx.x;
    int c = threadIdx.x * 4;
    float4 v = *(const float4*)(Wih + (size_t)j * (2 * Hh) + c);
    *(uint2*)(g_Wihembbf + (size_t)j * Hh + c) = f4_to_bf8(v);
}

__global__ __launch_bounds__(256) void conv_wcat_kernel(
    const float* __restrict__ Wq, const float* __restrict__ Whh)
{
    int r = blockIdx.x;
    const float* src = (r < Hh) ? (Wq + (size_t)r * Hh) : (Whh + (size_t)(r - Hh) * Hh);
    int c = threadIdx.x * 4;
    float4 v = *(const float4*)(src + c);
    uint2 hi, lo;
    split_f4(v, &hi, &lo);
    *(uint2*)(g_Wcat_hi + (size_t)r * Hh + c) = hi;
    *(uint2*)(g_Wcat_lo + (size_t)r * Hh + c) = lo;
}

__global__ __launch_bounds__(256) void conv_split_kernel(
    const float* __restrict__ src, __nv_bfloat16* __restrict__ dhi,
    __nv_bfloat16* __restrict__ dlo)
{
    int r = blockIdx.x;
    int c = threadIdx.x * 4;
    float4 v = *(const float4*)(src + (size_t)r * Hh + c);
    uint2 hi, lo;
    split_f4(v, &hi, &lo);
    *(uint2*)(dhi + (size_t)r * Hh + c) = hi;
    *(uint2*)(dlo + (size_t)r * Hh + c) = lo;
}

__global__ __launch_bounds__(256) void conv_wcp_kernel(const float* __restrict__ Wih)
{
    int cidx = blockIdx.x;
    int J = cidx / 384;
    int r = cidx % 384;
    int g = r >> 7;
    int l = r & 127;
    int j = J * 128 + l;
    const float* src = Wih + (size_t)(g * Hh + j) * (2 * Hh) + Hh;
    int c = threadIdx.x * 4;
    float4 v = *(const float4*)(src + c);
    uint2 hi, lo;
    split_f4(v, &hi, &lo);
    *(uint2*)(g_Wcp_hi + (size_t)cidx * Hh + c) = hi;
    *(uint2*)(g_Wcp_lo + (size_t)cidx * Hh + c) = lo;
}

__global__ __launch_bounds__(256) void gather_emb_kernel(
    const float* __restrict__ emb, const int* __restrict__ tgt)
{
    int r = blockIdx.x;
    int t = r >> 4, b = r & 15;
    int tok = (t == 0) ? BOSTOK : tgt[b * Tt + (t - 1)];
    int c = threadIdx.x * 4;
    float4 v = *(const float4*)(emb + (size_t)tok * Hh + c);
    *(uint2*)(g_embbf + (size_t)r * Hh + c) = f4_to_bf8(v);
}

// ---------------- h0 init (also resets barriers) / hT copy ----------------
__global__ void init_h_kernel(const float* __restrict__ h0) {
    int i = blockIdx.x * 256 + threadIdx.x;
    if (i == 0) g_barcnt = 0;
    if (i < 16 * 32) g_gbars[i] = 0;
    if (i < Bb * Hh) {
        float v = h0[i];
        g_H[i] = v;
        __nv_bfloat16 hi = __float2bfloat16(v);
        g_hhi[i] = hi;
        g_hlo[i] = __float2bfloat16(v - __bfloat162float(hi));
    }
}
__global__ void copy_hT_kernel(float* __restrict__ dst) {
    int i = blockIdx.x * 256 + threadIdx.x;
    if (i < Bb * Hh) dst[i] = g_H[(size_t)Tt * Bb * Hh + i];
}

// ---------------- mma primitive ----------------
__device__ __forceinline__ void mma16816(float* c, unsigned int a0, unsigned int a1,
                                         unsigned int a2, unsigned int a3,
                                         unsigned int b0, unsigned int b1)
{
    asm volatile(
        "mma.sync.aligned.m16n8k16.row.col.f32.bf16.bf16.f32 "
        "{%0,%1,%2,%3}, {%4,%5,%6,%7}, {%8,%9}, {%0,%1,%2,%3};\n"
        : "+f"(c[0]), "+f"(c[1]), "+f"(c[2]), "+f"(c[3])
        : "r"(a0), "r"(a1), "r"(a2), "r"(a3), "r"(b0), "r"(b1));
}

// ---- big bf16 TC GEMM: ldmatrix fragments, 4-stage cp.async, 1 sync/iter ----
#define MMA_SMEM (4 * 128 * 40 * 2 + 4 * 64 * 40 * 2)
__global__ __launch_bounds__(256) void bf16_mma_kernel(
    const __nv_bfloat16* __restrict__ A, const __nv_bfloat16* __restrict__ Bm,
    const float* __restrict__ bias, float* __restrict__ out,
    float2* __restrict__ lsep, int N, int remap)
{
    extern __shared__ __align__(16) __nv_bfloat16 smem[];
    __nv_bfloat16 (*sA)[128][40] = (__nv_bfloat16(*)[128][40])smem;
    __nv_bfloat16 (*sB)[64][40]  = (__nv_bfloat16(*)[64][40])(smem + 4 * 128 * 40);

    const int tid = threadIdx.x;
    const int warp = tid >> 5;
    const int lane = tid & 31;
    const int wm = (warp & 3) * 32;
    const int wn = (warp >> 2) * 32;
    const int bm = blockIdx.y * 128;
    const int bn = blockIdx.x * 64;

    const int lr = tid >> 2;
    const int lc = (tid & 3) * 8;
    const int aRow = (lane & 7) + ((lane >> 3) & 1) * 8;
    const int aCol = ((lane >> 4) & 1) * 8;
    const int bRow = (lane & 7) + ((lane >> 4) & 1) * 8;
    const int bCol = ((lane >> 3) & 1) * 8;

    const __nv_bfloat16* Abase = A + (size_t)(bm + lr) * Hh + lc;
    const __nv_bfloat16* A2base = A + (size_t)(bm + lr + 64) * Hh + lc;
    const __nv_bfloat16* Bbase = Bm + (size_t)(bn + lr) * Hh + lc;

    float acc[2][4][4] = {};
    const int row = lane >> 2;
    const int kc = (lane & 3) * 2;

    auto issue = [&](int st, int k0) {
        CPA16(smem_u32p(&sA[st][lr][lc]), Abase + k0);
        CPA16(smem_u32p(&sA[st][lr + 64][lc]), A2base + k0);
        CPA16(smem_u32p(&sB[st][lr][lc]), Bbase + k0);
        CPA_COMMIT();
    };

    issue(0, 0);
    issue(1, 32);
    for (int k = 0; k < 32; k++) {
        const int st = k & 3;
        if (k + 2 < 32) { issue((k + 2) & 3, (k + 2) * 32); CPA_WAIT(2); }
        else if (k + 2 == 32) CPA_WAIT(1);
        else CPA_WAIT(0);
        __syncthreads();
#pragma unroll
        for (int kk = 0; kk < 32; kk += 16) {
            unsigned int a[2][4], b[4][2];
#pragma unroll
            for (int mf = 0; mf < 2; mf++)
                ldsm_x4(a[mf], smem_u32p(&sA[st][wm + mf * 16 + aRow][kk + aCol]));
#pragma unroll
            for (int nfp = 0; nfp < 2; nfp++) {
                unsigned int tmp[4];
                ldsm_x4(tmp, smem_u32p(&sB[st][wn + nfp * 16 + bRow][kk + bCol]));
                b[2 * nfp][0] = tmp[0]; b[2 * nfp][1] = tmp[1];
                b[2 * nfp + 1][0] = tmp[2]; b[2 * nfp + 1][1] = tmp[3];
            }
#pragma unroll
            for (int mf = 0; mf < 2; mf++)
#pragma unroll
                for (int nf = 0; nf < 4; nf++)
                    mma16816(acc[mf][nf], a[mf][0], a[mf][1], a[mf][2], a[mf][3],
                             b[nf][0], b[nf][1]);
        }
    }

    float mx[4] = {-FLT_MAX, -FLT_MAX, -FLT_MAX, -FLT_MAX};
    float se[4] = {0.f, 0.f, 0.f, 0.f};
#pragma unroll
    for (int mf = 0; mf < 2; mf++) {
#pragma unroll
        for (int nf = 0; nf < 4; nf++) {
            int gm = bm + wm + mf * 16 + row;
            int gn = bn + wn + nf * 8 + kc;
            float bi0 = bias[gn], bi1 = bias[gn + 1];
            float x0 = acc[mf][nf][0] + bi0, x1 = acc[mf][nf][1] + bi1;
            float x2 = acc[mf][nf][2] + bi0, x3 = acc[mf][nf][3] + bi1;
            int o0 = remap ? ((gm & 15) * Tt + (gm >> 4)) : gm;
            int gm2 = gm + 8;
            int o1 = remap ? ((gm2 & 15) * Tt + (gm2 >> 4)) : gm2;
            *(float2*)(out + (size_t)o0 * N + gn) = make_float2(x0, x1);
            *(float2*)(out + (size_t)o1 * N + gn) = make_float2(x2, x3);
            if (lsep) {
                int r0i = mf * 2, r1i = mf * 2 + 1;
                float nm0 = fmaxf(mx[r0i], fmaxf(x0, x1));
                se[r0i] = se[r0i] * __expf(mx[r0i] - nm0) + __expf(x0 - nm0) + __expf(x1 - nm0);
                mx[r0i] = nm0;
                float nm1 = fmaxf(mx[r1i], fmaxf(x2, x3));
                se[r1i] = se[r1i] * __expf(mx[r1i] - nm1) + __expf(x2 - nm1) + __expf(x3 - nm1);
                mx[r1i] = nm1;
            }
        }
    }

    if (lsep) {
#pragma unroll
        for (int rr = 0; rr < 4; rr++) {
#pragma unroll
            for (int o = 1; o <= 2; o <<= 1) {
                float m2 = __shfl_xor_sync(~0u, mx[rr], o);
                float s2 = __shfl_xor_sync(~0u, se[rr], o);
                float nm = fmaxf(mx[rr], m2);
                se[rr] = se[rr] * __expf(mx[rr] - nm) + s2 * __expf(m2 - nm);
                mx[rr] = nm;
            }
        }
        __syncthreads();
        float2 (*sLse)[128] = (float2(*)[128])smem;
        if ((lane & 3) == 0) {
#pragma unroll
            for (int rr = 0; rr < 4; rr++) {
                int mrow = wm + (rr >> 1) * 16 + row + (rr & 1) * 8;
                sLse[warp >> 2][mrow] = make_float2(mx[rr], se[rr]);
            }
        }
        __syncthreads();
        if (tid < 128) {
            float2 p0 = sLse[0][tid], p1 = sLse[1][tid];
            float nm = fmaxf(p0.x, p1.x);
            float s = p0.y * __expf(p0.x - nm) + p1.y * __expf(p1.x - nm);
            int gm = bm + tid;
            int o = remap ? ((gm & 15) * Tt + (gm >> 4)) : gm;
            lsep[(size_t)o * gridDim.x + blockIdx.x] = make_float2(nm, s);
        }
    }
}

// ---- split GEMM (generic): out(fp32) = Ah@Bh^T + Ah@Bl^T + Al@Bh^T ----------
#define SPLIT_SMEM 61440
__global__ __launch_bounds__(256) void split_mma_kernel(
    const __nv_bfloat16* __restrict__ Ahp, const __nv_bfloat16* __restrict__ Alp,
    const __nv_bfloat16* __restrict__ Bhp, const __nv_bfloat16* __restrict__ Blp,
    float* __restrict__ out, int N)
{
    extern __shared__ __align__(16) __nv_bfloat16 sm[];
    __nv_bfloat16 (*sAh)[128][40] = (__nv_bfloat16(*)[128][40])sm;
    __nv_bfloat16 (*sAl)[128][40] = (__nv_bfloat16(*)[128][40])(sm + 2 * 128 * 40);
    __nv_bfloat16 (*sBh)[64][40]  = (__nv_bfloat16(*)[64][40]) (sm + 4 * 128 * 40);
    __nv_bfloat16 (*sBl)[64][40]  = (__nv_bfloat16(*)[64][40]) (sm + 4 * 128 * 40 + 2 * 64 * 40);

    const int tid = threadIdx.x;
    const int warp = tid >> 5;
    const int lane = tid & 31;
    const int wm = (warp & 3) * 32;
    const int wn = (warp >> 2) * 32;
    const int bm = blockIdx.y * 128;
    const int bn = blockIdx.x * 64;
    const int lr = tid >> 2;
    const int lc = (tid & 3) * 8;
    const int row = lane >> 2;
    const int kc = (lane & 3) * 2;
    const int aRow = (lane & 7) + ((lane >> 3) & 1) * 8;
    const int aCol = ((lane >> 4) & 1) * 8;
    const int bRow = (lane & 7) + ((lane >> 4) & 1) * 8;
    const int bCol = ((lane >> 3) & 1) * 8;

    const __nv_bfloat16* Ah1 = Ahp + (size_t)(bm + lr) * Hh + lc;
    const __nv_bfloat16* Ah2 = Ahp + (size_t)(bm + lr + 64) * Hh + lc;
    const __nv_bfloat16* Al1 = Alp + (size_t)(bm + lr) * Hh + lc;
    const __nv_bfloat16* Al2 = Alp + (size_t)(bm + lr + 64) * Hh + lc;
    const __nv_bfloat16* Bh1 = Bhp + (size_t)(bn + lr) * Hh + lc;
    const __nv_bfloat16* Bl1 = Blp + (size_t)(bn + lr) * Hh + lc;

    float acc[2][4][4] = {};

    auto issue = [&](int st, int k0) {
        CPA16(smem_u32p(&sAh[st][lr][lc]),      Ah1 + k0);
        CPA16(smem_u32p(&sAh[st][lr + 64][lc]), Ah2 + k0);
        CPA16(smem_u32p(&sAl[st][lr][lc]),      Al1 + k0);
        CPA16(smem_u32p(&sAl[st][lr + 64][lc]), Al2 + k0);
        CPA16(smem_u32p(&sBh[st][lr][lc]),      Bh1 + k0);
        CPA16(smem_u32p(&sBl[st][lr][lc]),      Bl1 + k0);
        CPA_COMMIT();
    };

    issue(0, 0);
    for (int k = 0; k < 32; k++) {
        const int st = k & 1;
        if (k + 1 < 32) { issue(st ^ 1, (k + 1) * 32); CPA_WAIT(1); }
        else            { CPA_WAIT(0); }
        __syncthreads();
#pragma unroll
        for (int kk = 0; kk < 32; kk += 16) {
            unsigned int ah[2][4], al[2][4], bh[4][2], bl[4][2];
#pragma unroll
            for (int mf = 0; mf < 2; mf++) {
                ldsm_x4(ah[mf], smem_u32p(&sAh[st][wm + mf * 16 + aRow][kk + aCol]));
                ldsm_x4(al[mf], smem_u32p(&sAl[st][wm + mf * 16 + aRow][kk + aCol]));
            }
#pragma unroll
            for (int nfp = 0; nfp < 2; nfp++) {
                unsigned int th[4], tl[4];
                ldsm_x4(th, smem_u32p(&sBh[st][wn + nfp * 16 + bRow][kk + bCol]));
                ldsm_x4(tl, smem_u32p(&sBl[st][wn + nfp * 16 + bRow][kk + bCol]));
                bh[2 * nfp][0] = th[0]; bh[2 * nfp][1] = th[1];
                bh[2 * nfp + 1][0] = th[2]; bh[2 * nfp + 1][1] = th[3];
                bl[2 * nfp][0] = tl[0]; bl[2 * nfp][1] = tl[1];
                bl[2 * nfp + 1][0] = tl[2]; bl[2 * nfp + 1][1] = tl[3];
            }
#pragma unroll
            for (int mf = 0; mf < 2; mf++)
#pragma unroll
                for (int nf = 0; nf < 4; nf++) {
                    mma16816(acc[mf][nf], ah[mf][0], ah[mf][1], ah[mf][2], ah[mf][3],
                             bh[nf][0], bh[nf][1]);
                    mma16816(acc[mf][nf], ah[mf][0], ah[mf][1], ah[mf][2], ah[mf][3],
                             bl[nf][0], bl[nf][1]);
                    mma16816(acc[mf][nf], al[mf][0], al[mf][1], al[mf][2], al[mf][3],
                             bh[nf][0], bh[nf][1]);
                }
        }
        __syncthreads();
    }

#pragma unroll
    for (int mf = 0; mf < 2; mf++) {
#pragma unroll
        for (int nf = 0; nf < 4; nf++) {
            int gm = bm + wm + mf * 16 + row;
            int gn = bn + wn + nf * 8 + kc;
            *(float2*)(out + (size_t)gm * N + gn) =
                make_float2(acc[mf][nf][0], acc[mf][nf][1]);
            *(float2*)(out + (size_t)(gm + 8) * N + gn) =
                make_float2(acc[mf][nf][2], acc[mf][nf][3]);
        }
    }
}

// ---------------- persistent decode loop: 128 blocks x 256 threads -----------
struct SmemA { __nv_bfloat16 Ah[4][16][72], Al[4][16][72], Bh[4][64][72], Bl[4][64][72]; };
struct SmemB { float q[Hh]; float v[Hh]; };
struct SmemC { float w[Ss]; float part[3][128]; float sred[4]; float sred2[4]; };
#define LOOP_SMEM 92160

__global__ __launch_bounds__(256) void loop_kernel(
    const float* __restrict__ vat, const float* __restrict__ bhh,
    float* __restrict__ attw)
{
    extern __shared__ __align__(16) unsigned char sraw[];

    const int g = blockIdx.x;
    const int tid = threadIdx.x;
    const int warp = tid >> 5;
    const int lane = tid & 31;
    const int row = lane >> 2;
    const int kc = (lane & 3) * 2;
    const int lrB = tid >> 2;
    const int lcB = (tid & 3) * 16;
    const int rA = (tid & 63) >> 2;
    const int cA = (tid & 3) * 16;
    const int wn = warp * 8;
    const int aRow = (lane & 7) + ((lane >> 3) & 1) * 8;
    const int aCol = ((lane >> 4) & 1) * 8;
    const int bRow2 = (lane & 7);
    const int bCol2 = ((lane >> 3) & 1) * 8;
    unsigned nfull = 0, ngrp = 0;

    const int ntA = g & 63, ksA = g >> 6;
    const int bnA = ntA * 64, kbA = ksA * 512;
    const __nv_bfloat16* gBhA = g_Wcat_hi + (size_t)(bnA + lrB) * Hh + kbA + lcB;
    const __nv_bfloat16* gBlA = g_Wcat_lo + (size_t)(bnA + lrB) * Hh + kbA + lcB;
    const __nv_bfloat16* gAhA = g_hhi + (size_t)rA * Hh + kbA + cA;
    const __nv_bfloat16* gAlA = g_hlo + (size_t)rA * Hh + kbA + cA;

    const int bB = g >> 3, sbB = (g & 7) * 16;
    const int bC = g >> 3, hcC = g & 7;

    for (int t = 0; t < Tt; t++) {
        // ================= stage A: [q | gh] partials (K-split 2) =============
        {
            SmemA& sa = *reinterpret_cast<SmemA*>(sraw);
            float c0[4] = {}, c1[4] = {}, c2[4] = {};

            auto issueA = [&](int st, int k0) {
                if (tid < 64) {
                    CPA16CG(smem_u32p(&sa.Ah[st][rA][cA]),     gAhA + k0);
                    CPA16CG(smem_u32p(&sa.Ah[st][rA][cA + 8]), gAhA + k0 + 8);
                } else if (tid < 128) {
                    CPA16CG(smem_u32p(&sa.Al[st][rA][cA]),     gAlA + k0);
                    CPA16CG(smem_u32p(&sa.Al[st][rA][cA + 8]), gAlA + k0 + 8);
                }
                CPA16(smem_u32p(&sa.Bh[st][lrB][lcB]),     gBhA + k0);
                CPA16(smem_u32p(&sa.Bh[st][lrB][lcB + 8]), gBhA + k0 + 8);
                CPA16(smem_u32p(&sa.Bl[st][lrB][lcB]),     gBlA + k0);
                CPA16(smem_u32p(&sa.Bl[st][lrB][lcB + 8]), gBlA + k0 + 8);
                CPA_COMMIT();
            };

            issueA(0, 0);
            issueA(1, 64);
            for (int k = 0; k < 8; k++) {
                const int st = k & 3;
                if (k + 2 < 8) { issueA((k + 2) & 3, (k + 2) * 64); CPA_WAIT(2); }
                else if (k + 2 == 8) CPA_WAIT(1);
                else CPA_WAIT(0);
                __syncthreads();
#pragma unroll
                for (int kk = 0; kk < 64; kk += 16) {
                    unsigned int ah[4], al[4], bh[2], bl[2];
                    ldsm_x4(ah, smem_u32p(&sa.Ah[st][aRow][kk + aCol]));
                    ldsm_x4(al, smem_u32p(&sa.Al[st][aRow][kk + aCol]));
                    ldsm_x2(bh, smem_u32p(&sa.Bh[st][wn + bRow2][kk + bCol2]));
                    ldsm_x2(bl, smem_u32p(&sa.Bl[st][wn + bRow2][kk + bCol2]));
                    mma16816(c0, ah[0], ah[1], ah[2], ah[3], bh[0], bh[1]);
                    mma16816(c1, ah[0], ah[1], ah[2], ah[3], bl[0], bl[1]);
                    mma16816(c2, al[0], al[1], al[2], al[3], bh[0], bh[1]);
                }
            }
            float v0 = c0[0] + c1[0] + c2[0];
            float v1 = c0[1] + c1[1] + c2[1];
            float v2 = c0[2] + c1[2] + c2[2];
            float v3 = c0[3] + c1[3] + c2[3];
            int gn = bnA + wn + kc;
            if (gn < Hh) {
                float* qd = g_q2[ksA];
                *(float2*)(qd + (size_t)row * Hh + gn)       = make_float2(v0, v1);
                *(float2*)(qd + (size_t)(row + 8) * Hh + gn) = make_float2(v2, v3);
            } else {
                int n = gn - Hh;
                float* gd = g_gh2[ksA];
                *(float2*)(gd + (size_t)row * 3 * Hh + n)       = make_float2(v0, v1);
                *(float2*)(gd + (size_t)(row + 8) * 3 * Hh + n) = make_float2(v2, v3);
            }
        }
        bar_full(nfull);

        // ================= stage B: scores (2 per warp, interleaved) ==========
        {
            SmemB& sb = *reinterpret_cast<SmemB*>(sraw);
            float4 q0 = __ldcg((const float4*)g_q2[0] + bB * 256 + tid);
            float4 q1 = __ldcg((const float4*)g_q2[1] + bB * 256 + tid);
            ((float4*)sb.q)[tid] = make_float4(q0.x + q1.x, q0.y + q1.y,
                                               q0.z + q1.z, q0.w + q1.w);
            ((float4*)sb.v)[tid] = __ldg((const float4*)vat + tid);
            __syncthreads();
            int s0 = sbB + warp * 2;
            const float4* kp0 = (const float4*)(g_kproj + (size_t)(bB * Ss + s0) * Hh);
            const float4* kp1 = kp0 + 256;
            float a0 = 0.f, a1 = 0.f;
#pragma unroll
            for (int i = 0; i < 8; i++) {
                int idx = i * 32 + lane;
                float4 ka = __ldg(kp0 + idx);
                float4 kb = __ldg(kp1 + idx);
                float4 q4 = ((const float4*)sb.q)[idx];
                float4 v4 = ((const float4*)sb.v)[idx];
                a0 = fmaf(v4.x, tanh_approx(q4.x + ka.x), a0);
                a1 = fmaf(v4.x, tanh_approx(q4.x + kb.x), a1);
                a0 = fmaf(v4.y, tanh_approx(q4.y + ka.y), a0);
                a1 = fmaf(v4.y, tanh_approx(q4.y + kb.y), a1);
                a0 = fmaf(v4.z, tanh_approx(q4.z + ka.z), a0);
                a1 = fmaf(v4.z, tanh_approx(q4.z + kb.z), a1);
                a0 = fmaf(v4.w, tanh_approx(q4.w + ka.w), a0);
                a1 = fmaf(v4.w, tanh_approx(q4.w + kb.w), a1);
            }
#pragma unroll
            for (int o = 16; o; o >>= 1) {
                a0 += __shfl_xor_sync(~0u, a0, o);
                a1 += __shfl_xor_sync(~0u, a1, o);
            }
            if (lane == 0) {
                g_scores[bB * Ss + s0] = a0;
                g_scores[bB * Ss + s0 + 1] = a1;
            }
        }
        bar_group(++ngrp);

        // ====== stage C': softmax + gx_ctx reduction + fused GRU + h write =====
        {
            SmemC& sc = *reinterpret_cast<SmemC*>(sraw);
            float sval = 0.f;
            if (tid < 128) {
                sval = __ldcg(g_scores + bC * Ss + tid);
                float mx = sval;
#pragma unroll
                for (int o = 16; o; o >>= 1) mx = fmaxf(mx, __shfl_xor_sync(~0u, mx, o));
                if ((tid & 31) == 0) sc.sred[tid >> 5] = mx;
            }
            __syncthreads();
            float mxx = fmaxf(fmaxf(sc.sred[0], sc.sred[1]), fmaxf(sc.sred[2], sc.sred[3]));
            float e = 0.f;
            if (tid < 128) {
                e = __expf(sval - mxx);
                float sm = e;
#pragma unroll
                for (int o = 16; o; o >>= 1) sm += __shfl_xor_sync(~0u, sm, o);
                if ((tid & 31) == 0) sc.sred2[tid >> 5] = sm;
            }
            __syncthreads();
            float tot = sc.sred2[0] + sc.sred2[1] + sc.sred2[2] + sc.sred2[3];
            if (tid < 128) {
                float wv = __fdividef(e, tot);
                sc.w[tid] = wv;
                if (hcC == 0) attw[((size_t)bC * Tt + t) * Ss + tid] = wv;
            }
            __syncthreads();

            const int l = tid & 127;
            const int sh = (tid >> 7) * 64;
            const float* ew = g_encWc + ((size_t)(bC * Ss + sh)) * (3 * Hh) + hcC * 384;
            const float* wp = sc.w + sh;
            float ar = 0.f, az = 0.f, an = 0.f;
#pragma unroll 8
            for (int s = 0; s < 64; s++) {
                float ws = wp[s];
                const float* rp = ew + (size_t)s * (3 * Hh);
                ar = fmaf(ws, __ldg(rp + l), ar);
                az = fmaf(ws, __ldg(rp + 128 + l), az);
                an = fmaf(ws, __ldg(rp + 256 + l), an);
            }
            if (tid >= 128) {
                sc.part[0][l] = ar; sc.part[1][l] = az; sc.part[2][l] = an;
            }
            __syncthreads();
            if (tid < 128) {
                ar += sc.part[0][l];
                az += sc.part[1][l];
                an += sc.part[2][l];
                const int j = hcC * 128 + l;
                const int r = t * Bb + bC;
                const float* gxe = g_gxemb + (size_t)r * 3 * Hh;
                const float* g0 = g_gh2[0] + (size_t)bC * 3 * Hh;
                const float* g1 = g_gh2[1] + (size_t)bC * 3 * Hh;
                float gx_r = ar + gxe[j];
                float gx_z = az + gxe[Hh + j];
                float gx_n = an + gxe[2 * Hh + j];
                float gh_r = __ldcg(g0 + j)          + __ldcg(g1 + j)          + bhh[j];
                float gh_z = __ldcg(g0 + Hh + j)     + __ldcg(g1 + Hh + j)     + bhh[Hh + j];
                float gh_n = __ldcg(g0 + 2 * Hh + j) + __ldcg(g1 + 2 * Hh + j) + bhh[2 * Hh + j];
                float rg = fast_sigmoid(gx_r + gh_r);
                float z  = fast_sigmoid(gx_z + gh_z);
                float nn = fast_tanh(gx_n + rg * gh_n);
                float hp = g_H[(size_t)t * Bb * Hh + bC * Hh + j];
                float hv = (1.f - z) * nn + z * hp;
                g_H[(size_t)(t + 1) * Bb * Hh + bC * Hh + j] = hv;
                g_Hbf[(size_t)r * Hh + j] = __float2bfloat16(hv);
                __nv_bfloat16 hi = __float2bfloat16(hv);
                g_hhi[bC * Hh + j] = hi;
                g_hlo[bC * Hh + j] = __float2bfloat16(hv - __bfloat162float(hi));
            }
        }
        bar_full(nfull);
    }
}

// -------- final: log_softmax using fused lse partials (vectorized subtract) --
__global__ __launch_bounds__(256) void logsoftmax_kernel(
    float* __restrict__ out, const float2* __restrict__ lsep, int ntile)
{
    const int o = blockIdx.x;
    float* row = out + (size_t)o * Vv;
    int tid = threadIdx.x;
    __shared__ float smax[8], ssum[8];

    float m = -FLT_MAX, s = 0.f;
    for (int i = tid; i < ntile; i += 256) {
        float2 p = lsep[(size_t)o * ntile + i];
        float nm = fmaxf(m, p.x);
        s = s * __expf(m - nm) + p.y * __expf(p.x - nm);
        m = nm;
    }
#pragma unroll
    for (int off = 16; off; off >>= 1) {
        float m2 = __shfl_xor_sync(~0u, m, off);
        float s2 = __shfl_xor_sync(~0u, s, off);
        float nm = fmaxf(m, m2);
        s = s * __expf(m - nm) + s2 * __expf(m2 - nm);
        m = nm;
    }
    if ((tid & 31) == 0) { smax[tid >> 5] = m; ssum[tid >> 5] = s; }
    __syncthreads();
    float M = smax[0];
#pragma unroll
    for (int i = 1; i < 8; i++) M = fmaxf(M, smax[i]);
    float S = 0.f;
#pragma unroll
    for (int i = 0; i < 8; i++) S += ssum[i] * __expf(smax[i] - M);

    float lse = M + logf(S);
    float4* row4 = (float4*)row;
    for (int v = tid; v < Vv / 4; v += 256) {
        float4 x = row4[v];
        x.x -= lse; x.y -= lse; x.z -= lse; x.w -= lse;
        row4[v] = x;
    }
}

// ---------------- orchestration ----------------
extern "C" void kernel_launch(void* const* d_in, const int* in_sizes, int n_in,
                              void* d_out, int out_size)
{
    const float* enc  = (const float*)d_in[0];
    const float* h0   = (const float*)d_in[1];
    const int*   tgt  = (const int*)  d_in[2];
    const float* emb  = (const float*)d_in[3];
    const float* Wq   = (const float*)d_in[4];
    const float* Wk   = (const float*)d_in[5];
    const float* vat  = (const float*)d_in[6];
    const float* Wih  = (const float*)d_in[7];
    const float* Whh  = (const float*)d_in[8];
    const float* bih  = (const float*)d_in[9];
    const float* bhh  = (const float*)d_in[10];
    const float* Wout = (const float*)d_in[11];
    const float* bout = (const float*)d_in[12];

    float* out       = (float*)d_out;
    float* out_hT    = out + (size_t)Bb * Tt * Vv;
    float* out_attw  = out_hT + (size_t)Bb * Hh;

    (void)in_sizes; (void)n_in; (void)out_size;

    cudaFuncSetAttribute(loop_kernel, cudaFuncAttributeMaxDynamicSharedMemorySize, LOOP_SMEM);
    cudaFuncSetAttribute(split_mma_kernel, cudaFuncAttributeMaxDynamicSharedMemorySize, SPLIT_SMEM);
    cudaFuncSetAttribute(bf16_mma_kernel, cudaFuncAttributeMaxDynamicSharedMemorySize, MMA_SMEM);

    // Phase 0: one-time conversions / precomputes
    conv_wout_kernel<<<4096, 256>>>(Wout);
    conv_wihemb_kernel<<<3 * Hh, 256>>>(Wih);
    conv_wcat_kernel<<<4 * Hh, 256>>>(Wq, Whh);
    conv_wcp_kernel<<<3 * Hh, 256>>>(Wih);
    gather_emb_kernel<<<Tt * Bb, 256>>>(emb, tgt);
    {
        __nv_bfloat16 *embbf, *wihembbf, *enc_hi, *enc_lo, *wcp_hi, *wcp_lo, *wk_hi, *wk_lo;
        float *gxemb_ptr, *encWc, *kproj;
        cudaGetSymbolAddress((void**)&embbf, g_embbf);
        cudaGetSymbolAddress((void**)&wihembbf, g_Wihembbf);
        cudaGetSymbolAddress((void**)&gxemb_ptr, g_gxemb);
        cudaGetSymbolAddress((void**)&enc_hi, g_enc_hi);
        cudaGetSymbolAddress((void**)&enc_lo, g_enc_lo);
        cudaGetSymbolAddress((void**)&wcp_hi, g_Wcp_hi);
        cudaGetSymbolAddress((void**)&wcp_lo, g_Wcp_lo);
        cudaGetSymbolAddress((void**)&wk_hi, g_Wk_hi);
        cudaGetSymbolAddress((void**)&wk_lo, g_Wk_lo);
        cudaGetSymbolAddress((void**)&encWc, g_encWc);
        cudaGetSymbolAddress((void**)&kproj, g_kproj);

        conv_split_kernel<<<Bb * Ss, 256>>>(enc, enc_hi, enc_lo);
        conv_split_kernel<<<Hh, 256>>>(Wk, wk_hi, wk_lo);

        bf16_mma_kernel<<<dim3(3 * Hh / 64, (Tt * Bb) / 128), 256, MMA_SMEM>>>(
            embbf, wihembbf, bih, gxemb_ptr, nullptr, 3 * Hh, 0);
        split_mma_kernel<<<dim3(3 * Hh / 64, (Bb * Ss) / 128), 256, SPLIT_SMEM>>>(
            enc_hi, enc_lo, wcp_hi, wcp_lo, encWc, 3 * Hh);
        split_mma_kernel<<<dim3(Hh / 64, (Bb * Ss) / 128), 256, SPLIT_SMEM>>>(
            enc_hi, enc_lo, wk_hi, wk_lo, kproj, Hh);
    }
    init_h_kernel<<<(Bb * Hh + 255) / 256, 256>>>(h0);

    // Phase 2: entire sequential decode in ONE persistent kernel (3 syncs/step)
    loop_kernel<<<GRIDB, 256, LOOP_SMEM>>>(vat, bhh, out_attw);

    copy_hT_kernel<<<(Bb * Hh + 255) / 256, 256>>>(out_hT);

    // Phase 3: logits (ldmatrix + 4-stage + fused lse partials) + log_softmax
    {
        __nv_bfloat16 *Abf, *Bbf;
        float2* lsep;
        cudaGetSymbolAddress((void**)&Abf, g_Hbf);
        cudaGetSymbolAddress((void**)&Bbf, g_Woutbf);
        cudaGetSymbolAddress((void**)&lsep, g_lsep);
        bf16_mma_kernel<<<dim3(Vv / 64, (Tt * Bb) / 128), 256, MMA_SMEM>>>(
            Abf, Bbf, bout, out, lsep, Vv, 1);
        logsoftmax_kernel<<<Bb * Tt, 256>>>(out, lsep, Vv / 64);
    }
}